// round 13
// baseline (speedup 1.0000x reference)
#include <cuda_runtime.h>
#include <math.h>

// Problem constants (match reference)
#define Tn   2048
#define Hd   1024
#define Id   704
#define Isd  1408
#define En   32
#define TOPG 3
#define Kn   6
#define CAPn 768

// Scratch (no cudaMalloc allowed)
__device__ int   g_topk_idx[Tn * Kn];
__device__ float g_topk_w[Tn * Kn];
__device__ int   g_rows[En * CAPn];   // flat assignment index per (expert, slot)
__device__ int   g_cnt[En];           // clamped count per expert
__device__ float g_h[(size_t)En * CAPn * Id];   // silu(g)*u per expert row
__device__ float g_hs[(size_t)Tn * Isd];        // shared-expert intermediate

__device__ __forceinline__ float siluf(float v) { return v / (1.0f + expf(-v)); }

// fp32 -> tf32 (round to nearest) kept in a float register (bit pattern)
__device__ __forceinline__ float to_tf32(float x) {
    unsigned r;
    asm("cvt.rna.tf32.f32 %0, %1;" : "=r"(r) : "f"(x));
    return __uint_as_float(r);
}

// one m16n8k8 tf32 mma, D += A*B
__device__ __forceinline__ void mma_tf32(float4& d, const float* a, const float* b) {
    asm volatile(
        "mma.sync.aligned.m16n8k8.row.col.f32.tf32.tf32.f32 "
        "{%0,%1,%2,%3}, {%4,%5,%6,%7}, {%8,%9}, {%0,%1,%2,%3};"
        : "+f"(d.x), "+f"(d.y), "+f"(d.z), "+f"(d.w)
        : "r"(__float_as_uint(a[0])), "r"(__float_as_uint(a[1])),
          "r"(__float_as_uint(a[2])), "r"(__float_as_uint(a[3])),
          "r"(__float_as_uint(b[0])), "r"(__float_as_uint(b[1])));
}

// ---------------------------------------------------------------------------
// Kernel 1: gating — logits, softmax, group top-3, expert top-6 (jax tie rules)
// one warp per token; lane == expert. Exact fp32 (topk is tie-sensitive).
// ---------------------------------------------------------------------------
__global__ void gate_kernel(const float* __restrict__ x, const float* __restrict__ gw) {
    int t = blockIdx.x;
    int lane = threadIdx.x;
    const float* xr = x + (size_t)t * Hd;
    const float* wr = gw + (size_t)lane * Hd;
    float acc = 0.f;
#pragma unroll 4
    for (int i = 0; i < Hd; i += 4) {
        float4 a = *(const float4*)(xr + i);
        float4 b = *(const float4*)(wr + i);
        acc += a.x * b.x + a.y * b.y + a.z * b.z + a.w * b.w;
    }
    float m = acc;
#pragma unroll
    for (int o = 16; o; o >>= 1) m = fmaxf(m, __shfl_xor_sync(0xffffffffu, m, o));
    float ex = expf(acc - m);
    float s = ex;
#pragma unroll
    for (int o = 16; o; o >>= 1) s += __shfl_xor_sync(0xffffffffu, s, o);
    float score = ex / s;

    float gs = score;
    gs = fmaxf(gs, __shfl_xor_sync(0xffffffffu, gs, 1));
    gs = fmaxf(gs, __shfl_xor_sync(0xffffffffu, gs, 2));
    float grp[8];
#pragma unroll
    for (int g = 0; g < 8; g++) grp[g] = __shfl_sync(0xffffffffu, gs, g * 4);

    bool keep[8];
#pragma unroll
    for (int g = 0; g < 8; g++) keep[g] = false;
    for (int r = 0; r < TOPG; r++) {
        float bv = -1.f; int bi = 0;
#pragma unroll
        for (int g = 0; g < 8; g++)
            if (!keep[g] && grp[g] > bv) { bv = grp[g]; bi = g; }
        keep[bi] = true;
    }
    float v = keep[lane >> 2] ? score : 0.0f;

    for (int r = 0; r < Kn; r++) {
        float bv = v; int bl = lane;
#pragma unroll
        for (int o = 16; o; o >>= 1) {
            float ov = __shfl_xor_sync(0xffffffffu, bv, o);
            int   ol = __shfl_xor_sync(0xffffffffu, bl, o);
            if (ov > bv || (ov == bv && ol < bl)) { bv = ov; bl = ol; }
        }
        if (lane == 0) { g_topk_idx[t * Kn + r] = bl; g_topk_w[t * Kn + r] = bv; }
        if (lane == bl) v = -1.0f;
    }
}

// ---------------------------------------------------------------------------
// Kernel 2: routing — stable rank within expert, capacity drop.
// ---------------------------------------------------------------------------
__global__ void route_kernel() {
    int e = blockIdx.x;
    __shared__ int wsum[8];
    int tid = threadIdx.x, lane = tid & 31, w = tid >> 5;
    int base = 0;
    for (int s = 0; s < Tn * Kn; s += 256) {
        int i = s + tid;
        int matched = (g_topk_idx[i] == e) ? 1 : 0;
        unsigned b = __ballot_sync(0xffffffffu, matched);
        if (lane == 0) wsum[w] = __popc(b);
        __syncthreads();
        int off = base;
        for (int j = 0; j < w; j++) off += wsum[j];
        int pos = off + __popc(b & ((1u << lane) - 1));
        if (matched && pos < CAPn) g_rows[e * CAPn + pos] = i;
        int tot = 0;
#pragma unroll
        for (int j = 0; j < 8; j++) tot += wsum[j];
        base += tot;
        __syncthreads();
    }
    if (tid == 0) g_cnt[e] = (base < CAPn) ? base : CAPn;
}

// ---------------------------------------------------------------------------
// Tensor-core gate/up GEMM: C = silu(A@Bg) * (A@Bu), tf32 mma m16n8k8.
// BM=128, BN=64, BK=16, 256 threads = 8 warps (4M x 2N), warp tile 32x32.
// GATHER=false: A = x (M=2048), B = sw_gate/sw_up (N=1408), C = g_hs
// GATHER=true : A = gathered x rows per expert, B = w_gate/w_up[e], C = g_h[e]
// ---------------------------------------------------------------------------
template <bool GATHER>
__global__ void __launch_bounds__(256, 2) gateup_tc(
    const float* __restrict__ X,
    const float* __restrict__ BgAll,
    const float* __restrict__ BuAll,
    int N, int Kd)
{
    __shared__ __align__(16) float As[128][20];   // [m][k], pad 4 -> frag loads conflict-free
    __shared__ __align__(16) float Bsg[16][72];   // [k][n], pad 8 -> frag loads conflict-free
    __shared__ __align__(16) float Bsu[16][72];
    __shared__ const float* Arow[128];

    const int tid  = threadIdx.x;
    const int lane = tid & 31, wid = tid >> 5;
    const int wM = wid & 3, wN = wid >> 2;
    const int g  = lane >> 2, tig = lane & 3;

    const int n0 = blockIdx.x * 64;
    const int m0 = blockIdx.y * 128;

    int e = 0, ne = 0;
    const float *Bg, *Bu;
    float* C;
    if (GATHER) {
        e = blockIdx.z;
        ne = g_cnt[e];
        if (m0 >= ne) return;
        Bg = BgAll + (size_t)e * Kd * N;
        Bu = BuAll + (size_t)e * Kd * N;
        C  = g_h + (size_t)e * CAPn * Id;
    } else {
        Bg = BgAll; Bu = BuAll; C = g_hs;
    }

    if (tid < 128) {
        int m = m0 + tid;
        const float* p = nullptr;
        if (GATHER) {
            if (m < ne) p = X + (size_t)(g_rows[e * CAPn + m] / Kn) * Hd;
        } else {
            p = X + (size_t)m * Kd;
        }
        Arow[tid] = p;
    }
    __syncthreads();

    float4 accg[2][4], accu[2][4];
#pragma unroll
    for (int mt = 0; mt < 2; mt++)
#pragma unroll
        for (int nt = 0; nt < 4; nt++) {
            accg[mt][nt] = make_float4(0.f, 0.f, 0.f, 0.f);
            accu[mt][nt] = make_float4(0.f, 0.f, 0.f, 0.f);
        }

    const int mA = tid >> 2;        // 0..63
    const int kq = tid & 3;         // 0..3
    const int kB = tid >> 4;        // 0..15
    const int nq = tid & 15;        // 0..15
    const float* pA0 = Arow[mA];
    const float* pA1 = Arow[mA + 64];

    for (int k0 = 0; k0 < Kd; k0 += 16) {
        // stage A (2 float4 per thread), convert to tf32
        {
            float4 v = make_float4(0.f, 0.f, 0.f, 0.f);
            if (pA0) v = *(const float4*)(pA0 + k0 + kq * 4);
            float4 w;
            w.x = to_tf32(v.x); w.y = to_tf32(v.y); w.z = to_tf32(v.z); w.w = to_tf32(v.w);
            *(float4*)&As[mA][kq * 4] = w;
            float4 u = make_float4(0.f, 0.f, 0.f, 0.f);
            if (pA1) u = *(const float4*)(pA1 + k0 + kq * 4);
            w.x = to_tf32(u.x); w.y = to_tf32(u.y); w.z = to_tf32(u.z); w.w = to_tf32(u.w);
            *(float4*)&As[mA + 64][kq * 4] = w;
        }
        // stage Bg/Bu (1 float4 each per thread)
        {
            float4 v = *(const float4*)(Bg + (size_t)(k0 + kB) * N + n0 + nq * 4);
            float4 w;
            w.x = to_tf32(v.x); w.y = to_tf32(v.y); w.z = to_tf32(v.z); w.w = to_tf32(v.w);
            *(float4*)&Bsg[kB][nq * 4] = w;
            v = *(const float4*)(Bu + (size_t)(k0 + kB) * N + n0 + nq * 4);
            w.x = to_tf32(v.x); w.y = to_tf32(v.y); w.z = to_tf32(v.z); w.w = to_tf32(v.w);
            *(float4*)&Bsu[kB][nq * 4] = w;
        }
        __syncthreads();

#pragma unroll
        for (int ks = 0; ks < 2; ks++) {
            const int kk = ks * 8;
            float af[2][4];
#pragma unroll
            for (int mt = 0; mt < 2; mt++) {
                int r = wM * 32 + mt * 16 + g;
                af[mt][0] = As[r][kk + tig];
                af[mt][1] = As[r + 8][kk + tig];
                af[mt][2] = As[r][kk + tig + 4];
                af[mt][3] = As[r + 8][kk + tig + 4];
            }
#pragma unroll
            for (int nt = 0; nt < 4; nt++) {
                int c = wN * 32 + nt * 8 + g;
                float bg[2] = { Bsg[kk + tig][c], Bsg[kk + tig + 4][c] };
                float bu[2] = { Bsu[kk + tig][c], Bsu[kk + tig + 4][c] };
#pragma unroll
                for (int mt = 0; mt < 2; mt++) {
                    mma_tf32(accg[mt][nt], af[mt], bg);
                    mma_tf32(accu[mt][nt], af[mt], bu);
                }
            }
        }
        __syncthreads();
    }

    // epilogue: silu(gate) * up, float2 stores (c0,c1 are adjacent columns)
#pragma unroll
    for (int mt = 0; mt < 2; mt++) {
        int r0 = m0 + wM * 32 + mt * 16 + g;
#pragma unroll
        for (int nt = 0; nt < 4; nt++) {
            int c = n0 + wN * 32 + nt * 8 + 2 * tig;
            if (!GATHER || r0 < ne) {
                float2 o;
                o.x = siluf(accg[mt][nt].x) * accu[mt][nt].x;
                o.y = siluf(accg[mt][nt].y) * accu[mt][nt].y;
                *(float2*)(C + (size_t)r0 * N + c) = o;
            }
            if (!GATHER || r0 + 8 < ne) {
                float2 o;
                o.x = siluf(accg[mt][nt].z) * accu[mt][nt].z;
                o.y = siluf(accg[mt][nt].w) * accu[mt][nt].w;
                *(float2*)(C + (size_t)(r0 + 8) * N + c) = o;
            }
        }
    }
}

// ---------------------------------------------------------------------------
// Tensor-core down GEMM. Same tile. N = Hd = 1024.
// SCATTER=false: out = g_hs @ sw_down (plain store, initializes out)
// SCATTER=true : y = g_h[e] @ w_down[e], out[tok] += w * y (atomics)
// ---------------------------------------------------------------------------
template <bool SCATTER>
__global__ void __launch_bounds__(256, 2) down_tc(
    const float* __restrict__ BAll,
    float* __restrict__ out,
    int Kd)
{
    __shared__ __align__(16) float As[128][20];
    __shared__ __align__(16) float Bs[16][72];
    __shared__ const float* Arow[128];

    const int tid  = threadIdx.x;
    const int lane = tid & 31, wid = tid >> 5;
    const int wM = wid & 3, wN = wid >> 2;
    const int g  = lane >> 2, tig = lane & 3;

    const int n0 = blockIdx.x * 64;
    const int m0 = blockIdx.y * 128;
    const int N = Hd;

    int e = 0, ne = 0;
    const float* B;
    const float* Abase;
    if (SCATTER) {
        e = blockIdx.z;
        ne = g_cnt[e];
        if (m0 >= ne) return;
        B = BAll + (size_t)e * Kd * N;
        Abase = g_h + (size_t)e * CAPn * Id;
    } else {
        B = BAll;
        Abase = g_hs;
    }

    if (tid < 128) {
        int m = m0 + tid;
        const float* p = nullptr;
        if (SCATTER) { if (m < ne) p = Abase + (size_t)m * Kd; }
        else p = Abase + (size_t)m * Kd;
        Arow[tid] = p;
    }
    __syncthreads();

    float4 acc[2][4];
#pragma unroll
    for (int mt = 0; mt < 2; mt++)
#pragma unroll
        for (int nt = 0; nt < 4; nt++) acc[mt][nt] = make_float4(0.f, 0.f, 0.f, 0.f);

    const int mA = tid >> 2;
    const int kq = tid & 3;
    const int kB = tid >> 4;
    const int nq = tid & 15;
    const float* pA0 = Arow[mA];
    const float* pA1 = Arow[mA + 64];

    for (int k0 = 0; k0 < Kd; k0 += 16) {
        {
            float4 v = make_float4(0.f, 0.f, 0.f, 0.f);
            if (pA0) v = *(const float4*)(pA0 + k0 + kq * 4);
            float4 w;
            w.x = to_tf32(v.x); w.y = to_tf32(v.y); w.z = to_tf32(v.z); w.w = to_tf32(v.w);
            *(float4*)&As[mA][kq * 4] = w;
            float4 u = make_float4(0.f, 0.f, 0.f, 0.f);
            if (pA1) u = *(const float4*)(pA1 + k0 + kq * 4);
            w.x = to_tf32(u.x); w.y = to_tf32(u.y); w.z = to_tf32(u.z); w.w = to_tf32(u.w);
            *(float4*)&As[mA + 64][kq * 4] = w;
        }
        {
            float4 v = *(const float4*)(B + (size_t)(k0 + kB) * N + n0 + nq * 4);
            float4 w;
            w.x = to_tf32(v.x); w.y = to_tf32(v.y); w.z = to_tf32(v.z); w.w = to_tf32(v.w);
            *(float4*)&Bs[kB][nq * 4] = w;
        }
        __syncthreads();

#pragma unroll
        for (int ks = 0; ks < 2; ks++) {
            const int kk = ks * 8;
            float af[2][4];
#pragma unroll
            for (int mt = 0; mt < 2; mt++) {
                int r = wM * 32 + mt * 16 + g;
                af[mt][0] = As[r][kk + tig];
                af[mt][1] = As[r + 8][kk + tig];
                af[mt][2] = As[r][kk + tig + 4];
                af[mt][3] = As[r + 8][kk + tig + 4];
            }
#pragma unroll
            for (int nt = 0; nt < 4; nt++) {
                int c = wN * 32 + nt * 8 + g;
                float bf[2] = { Bs[kk + tig][c], Bs[kk + tig + 4][c] };
#pragma unroll
                for (int mt = 0; mt < 2; mt++) mma_tf32(acc[mt][nt], af[mt], bf);
            }
        }
        __syncthreads();
    }

#pragma unroll
    for (int mt = 0; mt < 2; mt++) {
        int r0 = m0 + wM * 32 + mt * 16 + g;
#pragma unroll
        for (int nt = 0; nt < 4; nt++) {
            int c = n0 + wN * 32 + nt * 8 + 2 * tig;
            if (SCATTER) {
                if (r0 < ne) {
                    int flat = g_rows[e * CAPn + r0];
                    float wgt = g_topk_w[flat];
                    float* op = out + (size_t)(flat / Kn) * Hd + c;
                    atomicAdd(op + 0, wgt * acc[mt][nt].x);
                    atomicAdd(op + 1, wgt * acc[mt][nt].y);
                }
                if (r0 + 8 < ne) {
                    int flat = g_rows[e * CAPn + r0 + 8];
                    float wgt = g_topk_w[flat];
                    float* op = out + (size_t)(flat / Kn) * Hd + c;
                    atomicAdd(op + 0, wgt * acc[mt][nt].z);
                    atomicAdd(op + 1, wgt * acc[mt][nt].w);
                }
            } else {
                float2 o;
                o.x = acc[mt][nt].x; o.y = acc[mt][nt].y;
                *(float2*)(out + (size_t)r0 * Hd + c) = o;
                o.x = acc[mt][nt].z; o.y = acc[mt][nt].w;
                *(float2*)(out + (size_t)(r0 + 8) * Hd + c) = o;
            }
        }
    }
}

// ---------------------------------------------------------------------------
// Entry point. Inputs (metadata order, all fp32):
// 0:x 1:gate_w 2:w_gate 3:w_up 4:w_down 5:sw_gate 6:sw_up 7:sw_down
// ---------------------------------------------------------------------------
extern "C" void kernel_launch(void* const* d_in, const int* in_sizes, int n_in,
                              void* d_out, int out_size) {
    const float* x       = (const float*)d_in[0];
    const float* gate_w  = (const float*)d_in[1];
    const float* w_gate  = (const float*)d_in[2];
    const float* w_up    = (const float*)d_in[3];
    const float* w_down  = (const float*)d_in[4];
    const float* sw_gate = (const float*)d_in[5];
    const float* sw_up   = (const float*)d_in[6];
    const float* sw_down = (const float*)d_in[7];
    float* out = (float*)d_out;

    gate_kernel<<<Tn, 32>>>(x, gate_w);
    route_kernel<<<En, 256>>>();

    // shared-expert gate/up: (2048 x 1408), K=1024
    gateup_tc<false><<<dim3(Isd / 64, Tn / 128, 1), 256>>>(x, sw_gate, sw_up, Isd, Hd);
    // routed gate/up per expert: (<=768 x 704), K=1024
    gateup_tc<true><<<dim3(Id / 64, CAPn / 128, En), 256>>>(x, w_gate, w_up, Id, Hd);

    // shared-expert down: out = g_hs @ sw_down (initializes every element of out)
    down_tc<false><<<dim3(Hd / 64, Tn / 128, 1), 256>>>(sw_down, out, Isd);
    // routed down + weighted scatter-add (stream-ordered after init)
    down_tc<true><<<dim3(Hd / 64, CAPn / 128, En), 256>>>(w_down, out, Id);
}

// round 14
// speedup vs baseline: 1.0042x; 1.0042x over previous
#include <cuda_runtime.h>
#include <math.h>

// Problem constants (match reference)
#define Tn   2048
#define Hd   1024
#define Id   704
#define Isd  1408
#define En   32
#define TOPG 3
#define Kn   6
#define CAPn 768

// Scratch (no cudaMalloc allowed)
__device__ int   g_topk_idx[Tn * Kn];
__device__ float g_topk_w[Tn * Kn];
__device__ int   g_rows[En * CAPn];   // flat assignment index per (expert, slot)
__device__ int   g_cnt[En];           // clamped count per expert
__device__ float g_h[(size_t)En * CAPn * Id];   // silu(g)*u per expert row
__device__ float g_hs[(size_t)Tn * Isd];        // shared-expert intermediate

__device__ __forceinline__ float siluf(float v) { return v / (1.0f + expf(-v)); }

// fp32 -> tf32 (round to nearest) kept in a float register (bit pattern)
__device__ __forceinline__ float to_tf32(float x) {
    unsigned r;
    asm("cvt.rna.tf32.f32 %0, %1;" : "=r"(r) : "f"(x));
    return __uint_as_float(r);
}

// one m16n8k8 tf32 mma, D += A*B
__device__ __forceinline__ void mma_tf32(float4& d, const float* a, const float* b) {
    asm volatile(
        "mma.sync.aligned.m16n8k8.row.col.f32.tf32.tf32.f32 "
        "{%0,%1,%2,%3}, {%4,%5,%6,%7}, {%8,%9}, {%0,%1,%2,%3};"
        : "+f"(d.x), "+f"(d.y), "+f"(d.z), "+f"(d.w)
        : "r"(__float_as_uint(a[0])), "r"(__float_as_uint(a[1])),
          "r"(__float_as_uint(a[2])), "r"(__float_as_uint(a[3])),
          "r"(__float_as_uint(b[0])), "r"(__float_as_uint(b[1])));
}

// ---------------------------------------------------------------------------
// Kernel 1: gating — logits, softmax, group top-3, expert top-6 (jax tie rules)
// one warp per token; lane == expert. Exact fp32 (topk is tie-sensitive).
// ---------------------------------------------------------------------------
__global__ void gate_kernel(const float* __restrict__ x, const float* __restrict__ gw) {
    int t = blockIdx.x;
    int lane = threadIdx.x;
    const float* xr = x + (size_t)t * Hd;
    const float* wr = gw + (size_t)lane * Hd;
    float acc = 0.f;
#pragma unroll 4
    for (int i = 0; i < Hd; i += 4) {
        float4 a = *(const float4*)(xr + i);
        float4 b = *(const float4*)(wr + i);
        acc += a.x * b.x + a.y * b.y + a.z * b.z + a.w * b.w;
    }
    float m = acc;
#pragma unroll
    for (int o = 16; o; o >>= 1) m = fmaxf(m, __shfl_xor_sync(0xffffffffu, m, o));
    float ex = expf(acc - m);
    float s = ex;
#pragma unroll
    for (int o = 16; o; o >>= 1) s += __shfl_xor_sync(0xffffffffu, s, o);
    float score = ex / s;

    float gs = score;
    gs = fmaxf(gs, __shfl_xor_sync(0xffffffffu, gs, 1));
    gs = fmaxf(gs, __shfl_xor_sync(0xffffffffu, gs, 2));
    float grp[8];
#pragma unroll
    for (int g = 0; g < 8; g++) grp[g] = __shfl_sync(0xffffffffu, gs, g * 4);

    bool keep[8];
#pragma unroll
    for (int g = 0; g < 8; g++) keep[g] = false;
    for (int r = 0; r < TOPG; r++) {
        float bv = -1.f; int bi = 0;
#pragma unroll
        for (int g = 0; g < 8; g++)
            if (!keep[g] && grp[g] > bv) { bv = grp[g]; bi = g; }
        keep[bi] = true;
    }
    float v = keep[lane >> 2] ? score : 0.0f;

    for (int r = 0; r < Kn; r++) {
        float bv = v; int bl = lane;
#pragma unroll
        for (int o = 16; o; o >>= 1) {
            float ov = __shfl_xor_sync(0xffffffffu, bv, o);
            int   ol = __shfl_xor_sync(0xffffffffu, bl, o);
            if (ov > bv || (ov == bv && ol < bl)) { bv = ov; bl = ol; }
        }
        if (lane == 0) { g_topk_idx[t * Kn + r] = bl; g_topk_w[t * Kn + r] = bv; }
        if (lane == bl) v = -1.0f;
    }
}

// ---------------------------------------------------------------------------
// Kernel 2: routing — stable rank within expert, capacity drop.
// ---------------------------------------------------------------------------
__global__ void route_kernel() {
    int e = blockIdx.x;
    __shared__ int wsum[8];
    int tid = threadIdx.x, lane = tid & 31, w = tid >> 5;
    int base = 0;
    for (int s = 0; s < Tn * Kn; s += 256) {
        int i = s + tid;
        int matched = (g_topk_idx[i] == e) ? 1 : 0;
        unsigned b = __ballot_sync(0xffffffffu, matched);
        if (lane == 0) wsum[w] = __popc(b);
        __syncthreads();
        int off = base;
        for (int j = 0; j < w; j++) off += wsum[j];
        int pos = off + __popc(b & ((1u << lane) - 1));
        if (matched && pos < CAPn) g_rows[e * CAPn + pos] = i;
        int tot = 0;
#pragma unroll
        for (int j = 0; j < 8; j++) tot += wsum[j];
        base += tot;
        __syncthreads();
    }
    if (tid == 0) g_cnt[e] = (base < CAPn) ? base : CAPn;
}

// ---------------------------------------------------------------------------
// Tensor-core gate/up GEMM: C = silu(A@Bg) * (A@Bu), tf32 mma m16n8k8.
// BM=128, BN=64, BK=16, 256 threads = 8 warps (4M x 2N), warp tile 32x32.
// GATHER=false: A = x (M=2048), B = sw_gate/sw_up (N=1408), C = g_hs
// GATHER=true : A = gathered x rows per expert, B = w_gate/w_up[e], C = g_h[e]
// ---------------------------------------------------------------------------
template <bool GATHER>
__global__ void __launch_bounds__(256, 2) gateup_tc(
    const float* __restrict__ X,
    const float* __restrict__ BgAll,
    const float* __restrict__ BuAll,
    int N, int Kd)
{
    __shared__ __align__(16) float As[128][20];   // [m][k], pad 4 -> frag loads conflict-free
    __shared__ __align__(16) float Bsg[16][72];   // [k][n], pad 8 -> frag loads conflict-free
    __shared__ __align__(16) float Bsu[16][72];
    __shared__ const float* Arow[128];

    const int tid  = threadIdx.x;
    const int lane = tid & 31, wid = tid >> 5;
    const int wM = wid & 3, wN = wid >> 2;
    const int g  = lane >> 2, tig = lane & 3;

    const int n0 = blockIdx.x * 64;
    const int m0 = blockIdx.y * 128;

    int e = 0, ne = 0;
    const float *Bg, *Bu;
    float* C;
    if (GATHER) {
        e = blockIdx.z;
        ne = g_cnt[e];
        if (m0 >= ne) return;
        Bg = BgAll + (size_t)e * Kd * N;
        Bu = BuAll + (size_t)e * Kd * N;
        C  = g_h + (size_t)e * CAPn * Id;
    } else {
        Bg = BgAll; Bu = BuAll; C = g_hs;
    }

    if (tid < 128) {
        int m = m0 + tid;
        const float* p = nullptr;
        if (GATHER) {
            if (m < ne) p = X + (size_t)(g_rows[e * CAPn + m] / Kn) * Hd;
        } else {
            p = X + (size_t)m * Kd;
        }
        Arow[tid] = p;
    }
    __syncthreads();

    float4 accg[2][4], accu[2][4];
#pragma unroll
    for (int mt = 0; mt < 2; mt++)
#pragma unroll
        for (int nt = 0; nt < 4; nt++) {
            accg[mt][nt] = make_float4(0.f, 0.f, 0.f, 0.f);
            accu[mt][nt] = make_float4(0.f, 0.f, 0.f, 0.f);
        }

    const int mA = tid >> 2;        // 0..63
    const int kq = tid & 3;         // 0..3
    const int kB = tid >> 4;        // 0..15
    const int nq = tid & 15;        // 0..15
    const float* pA0 = Arow[mA];
    const float* pA1 = Arow[mA + 64];

    for (int k0 = 0; k0 < Kd; k0 += 16) {
        // stage A (2 float4 per thread), convert to tf32
        {
            float4 v = make_float4(0.f, 0.f, 0.f, 0.f);
            if (pA0) v = *(const float4*)(pA0 + k0 + kq * 4);
            float4 w;
            w.x = to_tf32(v.x); w.y = to_tf32(v.y); w.z = to_tf32(v.z); w.w = to_tf32(v.w);
            *(float4*)&As[mA][kq * 4] = w;
            float4 u = make_float4(0.f, 0.f, 0.f, 0.f);
            if (pA1) u = *(const float4*)(pA1 + k0 + kq * 4);
            w.x = to_tf32(u.x); w.y = to_tf32(u.y); w.z = to_tf32(u.z); w.w = to_tf32(u.w);
            *(float4*)&As[mA + 64][kq * 4] = w;
        }
        // stage Bg/Bu (1 float4 each per thread)
        {
            float4 v = *(const float4*)(Bg + (size_t)(k0 + kB) * N + n0 + nq * 4);
            float4 w;
            w.x = to_tf32(v.x); w.y = to_tf32(v.y); w.z = to_tf32(v.z); w.w = to_tf32(v.w);
            *(float4*)&Bsg[kB][nq * 4] = w;
            v = *(const float4*)(Bu + (size_t)(k0 + kB) * N + n0 + nq * 4);
            w.x = to_tf32(v.x); w.y = to_tf32(v.y); w.z = to_tf32(v.z); w.w = to_tf32(v.w);
            *(float4*)&Bsu[kB][nq * 4] = w;
        }
        __syncthreads();

#pragma unroll
        for (int ks = 0; ks < 2; ks++) {
            const int kk = ks * 8;
            float af[2][4];
#pragma unroll
            for (int mt = 0; mt < 2; mt++) {
                int r = wM * 32 + mt * 16 + g;
                af[mt][0] = As[r][kk + tig];
                af[mt][1] = As[r + 8][kk + tig];
                af[mt][2] = As[r][kk + tig + 4];
                af[mt][3] = As[r + 8][kk + tig + 4];
            }
#pragma unroll
            for (int nt = 0; nt < 4; nt++) {
                int c = wN * 32 + nt * 8 + g;
                float bg[2] = { Bsg[kk + tig][c], Bsg[kk + tig + 4][c] };
                float bu[2] = { Bsu[kk + tig][c], Bsu[kk + tig + 4][c] };
#pragma unroll
                for (int mt = 0; mt < 2; mt++) {
                    mma_tf32(accg[mt][nt], af[mt], bg);
                    mma_tf32(accu[mt][nt], af[mt], bu);
                }
            }
        }
        __syncthreads();
    }

    // epilogue: silu(gate) * up, float2 stores (c0,c1 are adjacent columns)
#pragma unroll
    for (int mt = 0; mt < 2; mt++) {
        int r0 = m0 + wM * 32 + mt * 16 + g;
#pragma unroll
        for (int nt = 0; nt < 4; nt++) {
            int c = n0 + wN * 32 + nt * 8 + 2 * tig;
            if (!GATHER || r0 < ne) {
                float2 o;
                o.x = siluf(accg[mt][nt].x) * accu[mt][nt].x;
                o.y = siluf(accg[mt][nt].y) * accu[mt][nt].y;
                *(float2*)(C + (size_t)r0 * N + c) = o;
            }
            if (!GATHER || r0 + 8 < ne) {
                float2 o;
                o.x = siluf(accg[mt][nt].z) * accu[mt][nt].z;
                o.y = siluf(accg[mt][nt].w) * accu[mt][nt].w;
                *(float2*)(C + (size_t)(r0 + 8) * N + c) = o;
            }
        }
    }
}

// ---------------------------------------------------------------------------
// Tensor-core down GEMM. Same tile. N = Hd = 1024.
// SCATTER=false: out = g_hs @ sw_down (plain store, initializes out)
// SCATTER=true : y = g_h[e] @ w_down[e], out[tok] += w * y (atomics)
// ---------------------------------------------------------------------------
template <bool SCATTER>
__global__ void __launch_bounds__(256, 2) down_tc(
    const float* __restrict__ BAll,
    float* __restrict__ out,
    int Kd)
{
    __shared__ __align__(16) float As[128][20];
    __shared__ __align__(16) float Bs[16][72];
    __shared__ const float* Arow[128];

    const int tid  = threadIdx.x;
    const int lane = tid & 31, wid = tid >> 5;
    const int wM = wid & 3, wN = wid >> 2;
    const int g  = lane >> 2, tig = lane & 3;

    const int n0 = blockIdx.x * 64;
    const int m0 = blockIdx.y * 128;
    const int N = Hd;

    int e = 0, ne = 0;
    const float* B;
    const float* Abase;
    if (SCATTER) {
        e = blockIdx.z;
        ne = g_cnt[e];
        if (m0 >= ne) return;
        B = BAll + (size_t)e * Kd * N;
        Abase = g_h + (size_t)e * CAPn * Id;
    } else {
        B = BAll;
        Abase = g_hs;
    }

    if (tid < 128) {
        int m = m0 + tid;
        const float* p = nullptr;
        if (SCATTER) { if (m < ne) p = Abase + (size_t)m * Kd; }
        else p = Abase + (size_t)m * Kd;
        Arow[tid] = p;
    }
    __syncthreads();

    float4 acc[2][4];
#pragma unroll
    for (int mt = 0; mt < 2; mt++)
#pragma unroll
        for (int nt = 0; nt < 4; nt++) acc[mt][nt] = make_float4(0.f, 0.f, 0.f, 0.f);

    const int mA = tid >> 2;
    const int kq = tid & 3;
    const int kB = tid >> 4;
    const int nq = tid & 15;
    const float* pA0 = Arow[mA];
    const float* pA1 = Arow[mA + 64];

    for (int k0 = 0; k0 < Kd; k0 += 16) {
        {
            float4 v = make_float4(0.f, 0.f, 0.f, 0.f);
            if (pA0) v = *(const float4*)(pA0 + k0 + kq * 4);
            float4 w;
            w.x = to_tf32(v.x); w.y = to_tf32(v.y); w.z = to_tf32(v.z); w.w = to_tf32(v.w);
            *(float4*)&As[mA][kq * 4] = w;
            float4 u = make_float4(0.f, 0.f, 0.f, 0.f);
            if (pA1) u = *(const float4*)(pA1 + k0 + kq * 4);
            w.x = to_tf32(u.x); w.y = to_tf32(u.y); w.z = to_tf32(u.z); w.w = to_tf32(u.w);
            *(float4*)&As[mA + 64][kq * 4] = w;
        }
        {
            float4 v = *(const float4*)(B + (size_t)(k0 + kB) * N + n0 + nq * 4);
            float4 w;
            w.x = to_tf32(v.x); w.y = to_tf32(v.y); w.z = to_tf32(v.z); w.w = to_tf32(v.w);
            *(float4*)&Bs[kB][nq * 4] = w;
        }
        __syncthreads();

#pragma unroll
        for (int ks = 0; ks < 2; ks++) {
            const int kk = ks * 8;
            float af[2][4];
#pragma unroll
            for (int mt = 0; mt < 2; mt++) {
                int r = wM * 32 + mt * 16 + g;
                af[mt][0] = As[r][kk + tig];
                af[mt][1] = As[r + 8][kk + tig];
                af[mt][2] = As[r][kk + tig + 4];
                af[mt][3] = As[r + 8][kk + tig + 4];
            }
#pragma unroll
            for (int nt = 0; nt < 4; nt++) {
                int c = wN * 32 + nt * 8 + g;
                float bf[2] = { Bs[kk + tig][c], Bs[kk + tig + 4][c] };
#pragma unroll
                for (int mt = 0; mt < 2; mt++) mma_tf32(acc[mt][nt], af[mt], bf);
            }
        }
        __syncthreads();
    }

#pragma unroll
    for (int mt = 0; mt < 2; mt++) {
        int r0 = m0 + wM * 32 + mt * 16 + g;
#pragma unroll
        for (int nt = 0; nt < 4; nt++) {
            int c = n0 + wN * 32 + nt * 8 + 2 * tig;
            if (SCATTER) {
                if (r0 < ne) {
                    int flat = g_rows[e * CAPn + r0];
                    float wgt = g_topk_w[flat];
                    float* op = out + (size_t)(flat / Kn) * Hd + c;
                    atomicAdd(op + 0, wgt * acc[mt][nt].x);
                    atomicAdd(op + 1, wgt * acc[mt][nt].y);
                }
                if (r0 + 8 < ne) {
                    int flat = g_rows[e * CAPn + r0 + 8];
                    float wgt = g_topk_w[flat];
                    float* op = out + (size_t)(flat / Kn) * Hd + c;
                    atomicAdd(op + 0, wgt * acc[mt][nt].z);
                    atomicAdd(op + 1, wgt * acc[mt][nt].w);
                }
            } else {
                float2 o;
                o.x = acc[mt][nt].x; o.y = acc[mt][nt].y;
                *(float2*)(out + (size_t)r0 * Hd + c) = o;
                o.x = acc[mt][nt].z; o.y = acc[mt][nt].w;
                *(float2*)(out + (size_t)(r0 + 8) * Hd + c) = o;
            }
        }
    }
}

// ---------------------------------------------------------------------------
// Entry point. Inputs (metadata order, all fp32):
// 0:x 1:gate_w 2:w_gate 3:w_up 4:w_down 5:sw_gate 6:sw_up 7:sw_down
// ---------------------------------------------------------------------------
extern "C" void kernel_launch(void* const* d_in, const int* in_sizes, int n_in,
                              void* d_out, int out_size) {
    const float* x       = (const float*)d_in[0];
    const float* gate_w  = (const float*)d_in[1];
    const float* w_gate  = (const float*)d_in[2];
    const float* w_up    = (const float*)d_in[3];
    const float* w_down  = (const float*)d_in[4];
    const float* sw_gate = (const float*)d_in[5];
    const float* sw_up   = (const float*)d_in[6];
    const float* sw_down = (const float*)d_in[7];
    float* out = (float*)d_out;

    gate_kernel<<<Tn, 32>>>(x, gate_w);
    route_kernel<<<En, 256>>>();

    // shared-expert gate/up: (2048 x 1408), K=1024
    gateup_tc<false><<<dim3(Isd / 64, Tn / 128, 1), 256>>>(x, sw_gate, sw_up, Isd, Hd);
    // routed gate/up per expert: (<=768 x 704), K=1024
    gateup_tc<true><<<dim3(Id / 64, CAPn / 128, En), 256>>>(x, w_gate, w_up, Id, Hd);

    // shared-expert down: out = g_hs @ sw_down (initializes every element of out)
    down_tc<false><<<dim3(Hd / 64, Tn / 128, 1), 256>>>(sw_down, out, Isd);
    // routed down + weighted scatter-add (stream-ordered after init)
    down_tc<true><<<dim3(Hd / 64, CAPn / 128, En), 256>>>(w_down, out, Id);
}

// round 15
// speedup vs baseline: 1.4023x; 1.3965x over previous
#include <cuda_runtime.h>
#include <math.h>

// Problem constants (match reference)
#define Tn   2048
#define Hd   1024
#define Id   704
#define Isd  1408
#define En   32
#define TOPG 3
#define Kn   6
#define CAPn 768

// Scratch (no cudaMalloc allowed)
__device__ int   g_topk_idx[Tn * Kn];
__device__ float g_topk_w[Tn * Kn];
__device__ int   g_rows[En * CAPn];   // flat assignment index per (expert, slot)
__device__ int   g_cnt[En];           // clamped count per expert
__device__ float g_h[(size_t)En * CAPn * Id];   // silu(g)*u per expert row
__device__ float g_hs[(size_t)Tn * Isd];        // shared-expert intermediate

__device__ __forceinline__ float siluf(float v) { return v / (1.0f + expf(-v)); }

// fp32 -> tf32 (round to nearest) kept in a float register (bit pattern)
__device__ __forceinline__ float to_tf32(float x) {
    unsigned r;
    asm("cvt.rna.tf32.f32 %0, %1;" : "=r"(r) : "f"(x));
    return __uint_as_float(r);
}
__device__ __forceinline__ float4 cvt4(float4 v) {
    float4 w;
    w.x = to_tf32(v.x); w.y = to_tf32(v.y); w.z = to_tf32(v.z); w.w = to_tf32(v.w);
    return w;
}

// one m16n8k8 tf32 mma, D += A*B
__device__ __forceinline__ void mma_tf32(float4& d, const float* a, const float* b) {
    asm volatile(
        "mma.sync.aligned.m16n8k8.row.col.f32.tf32.tf32.f32 "
        "{%0,%1,%2,%3}, {%4,%5,%6,%7}, {%8,%9}, {%0,%1,%2,%3};"
        : "+f"(d.x), "+f"(d.y), "+f"(d.z), "+f"(d.w)
        : "r"(__float_as_uint(a[0])), "r"(__float_as_uint(a[1])),
          "r"(__float_as_uint(a[2])), "r"(__float_as_uint(a[3])),
          "r"(__float_as_uint(b[0])), "r"(__float_as_uint(b[1])));
}

// ---------------------------------------------------------------------------
// Kernel 1: gating — logits, softmax, group top-3, expert top-6 (jax tie rules)
// one warp per token; lane == expert. Exact fp32 (topk is tie-sensitive).
// ---------------------------------------------------------------------------
__global__ void gate_kernel(const float* __restrict__ x, const float* __restrict__ gw) {
    int t = blockIdx.x;
    int lane = threadIdx.x;
    const float* xr = x + (size_t)t * Hd;
    const float* wr = gw + (size_t)lane * Hd;
    float acc = 0.f;
#pragma unroll 4
    for (int i = 0; i < Hd; i += 4) {
        float4 a = *(const float4*)(xr + i);
        float4 b = *(const float4*)(wr + i);
        acc += a.x * b.x + a.y * b.y + a.z * b.z + a.w * b.w;
    }
    float m = acc;
#pragma unroll
    for (int o = 16; o; o >>= 1) m = fmaxf(m, __shfl_xor_sync(0xffffffffu, m, o));
    float ex = expf(acc - m);
    float s = ex;
#pragma unroll
    for (int o = 16; o; o >>= 1) s += __shfl_xor_sync(0xffffffffu, s, o);
    float score = ex / s;

    float gs = score;
    gs = fmaxf(gs, __shfl_xor_sync(0xffffffffu, gs, 1));
    gs = fmaxf(gs, __shfl_xor_sync(0xffffffffu, gs, 2));
    float grp[8];
#pragma unroll
    for (int g = 0; g < 8; g++) grp[g] = __shfl_sync(0xffffffffu, gs, g * 4);

    bool keep[8];
#pragma unroll
    for (int g = 0; g < 8; g++) keep[g] = false;
    for (int r = 0; r < TOPG; r++) {
        float bv = -1.f; int bi = 0;
#pragma unroll
        for (int g = 0; g < 8; g++)
            if (!keep[g] && grp[g] > bv) { bv = grp[g]; bi = g; }
        keep[bi] = true;
    }
    float v = keep[lane >> 2] ? score : 0.0f;

    for (int r = 0; r < Kn; r++) {
        float bv = v; int bl = lane;
#pragma unroll
        for (int o = 16; o; o >>= 1) {
            float ov = __shfl_xor_sync(0xffffffffu, bv, o);
            int   ol = __shfl_xor_sync(0xffffffffu, bl, o);
            if (ov > bv || (ov == bv && ol < bl)) { bv = ov; bl = ol; }
        }
        if (lane == 0) { g_topk_idx[t * Kn + r] = bl; g_topk_w[t * Kn + r] = bv; }
        if (lane == bl) v = -1.0f;
    }
}

// ---------------------------------------------------------------------------
// Kernel 2: routing — stable rank within expert, capacity drop.
// ---------------------------------------------------------------------------
__global__ void route_kernel() {
    int e = blockIdx.x;
    __shared__ int wsum[8];
    int tid = threadIdx.x, lane = tid & 31, w = tid >> 5;
    int base = 0;
    for (int s = 0; s < Tn * Kn; s += 256) {
        int i = s + tid;
        int matched = (g_topk_idx[i] == e) ? 1 : 0;
        unsigned b = __ballot_sync(0xffffffffu, matched);
        if (lane == 0) wsum[w] = __popc(b);
        __syncthreads();
        int off = base;
        for (int j = 0; j < w; j++) off += wsum[j];
        int pos = off + __popc(b & ((1u << lane) - 1));
        if (matched && pos < CAPn) g_rows[e * CAPn + pos] = i;
        int tot = 0;
#pragma unroll
        for (int j = 0; j < 8; j++) tot += wsum[j];
        base += tot;
        __syncthreads();
    }
    if (tid == 0) g_cnt[e] = (base < CAPn) ? base : CAPn;
}

// ---------------------------------------------------------------------------
// Tensor-core gate/up GEMM: C = silu(A@Bg) * (A@Bu), tf32 mma m16n8k8.
// BM=128, BN=64, BK=16, 256 threads = 8 warps (4M x 2N), warp tile 32x32.
// Double-buffered smem, register prefetch, one __syncthreads per k-step.
// ---------------------------------------------------------------------------
template <bool GATHER>
__global__ void __launch_bounds__(256, 2) gateup_tc(
    const float* __restrict__ X,
    const float* __restrict__ BgAll,
    const float* __restrict__ BuAll,
    int N, int Kd)
{
    __shared__ __align__(16) float As[2][128][20];
    __shared__ __align__(16) float Bsg[2][16][72];
    __shared__ __align__(16) float Bsu[2][16][72];
    __shared__ const float* Arow[128];

    const int tid  = threadIdx.x;
    const int lane = tid & 31, wid = tid >> 5;
    const int wM = wid & 3, wN = wid >> 2;
    const int g  = lane >> 2, tig = lane & 3;

    const int n0 = blockIdx.x * 64;
    const int m0 = blockIdx.y * 128;

    int e = 0, ne = 0;
    const float *Bg, *Bu;
    float* C;
    if (GATHER) {
        e = blockIdx.z;
        ne = g_cnt[e];
        if (m0 >= ne) return;
        Bg = BgAll + (size_t)e * Kd * N;
        Bu = BuAll + (size_t)e * Kd * N;
        C  = g_h + (size_t)e * CAPn * Id;
    } else {
        Bg = BgAll; Bu = BuAll; C = g_hs;
    }

    if (tid < 128) {
        int m = m0 + tid;
        const float* p = nullptr;
        if (GATHER) {
            if (m < ne) p = X + (size_t)(g_rows[e * CAPn + m] / Kn) * Hd;
        } else {
            p = X + (size_t)m * Kd;
        }
        Arow[tid] = p;
    }
    __syncthreads();

    float4 accg[2][4], accu[2][4];
#pragma unroll
    for (int mt = 0; mt < 2; mt++)
#pragma unroll
        for (int nt = 0; nt < 4; nt++) {
            accg[mt][nt] = make_float4(0.f, 0.f, 0.f, 0.f);
            accu[mt][nt] = make_float4(0.f, 0.f, 0.f, 0.f);
        }

    const int mA = tid >> 2;        // 0..63
    const int kq = tid & 3;         // 0..3
    const int kB = tid >> 4;        // 0..15
    const int nq = tid & 15;        // 0..15
    const float* pA0 = Arow[mA];
    const float* pA1 = Arow[mA + 64];
    const float4 z4 = make_float4(0.f, 0.f, 0.f, 0.f);

    float4 rA0, rA1, rBg, rBu;

    auto LDGf = [&](int k0) {
        rA0 = pA0 ? *(const float4*)(pA0 + k0 + kq * 4) : z4;
        rA1 = pA1 ? *(const float4*)(pA1 + k0 + kq * 4) : z4;
        const size_t bo = (size_t)(k0 + kB) * N + n0 + nq * 4;
        rBg = *(const float4*)(Bg + bo);
        rBu = *(const float4*)(Bu + bo);
    };
    auto STSf = [&](int buf) {
        *(float4*)&As[buf][mA][kq * 4]       = cvt4(rA0);
        *(float4*)&As[buf][mA + 64][kq * 4]  = cvt4(rA1);
        *(float4*)&Bsg[buf][kB][nq * 4]      = cvt4(rBg);
        *(float4*)&Bsu[buf][kB][nq * 4]      = cvt4(rBu);
    };
    auto MMAf = [&](int buf) {
#pragma unroll
        for (int ks = 0; ks < 2; ks++) {
            const int kk = ks * 8;
            float af[2][4];
#pragma unroll
            for (int mt = 0; mt < 2; mt++) {
                int r = wM * 32 + mt * 16 + g;
                af[mt][0] = As[buf][r][kk + tig];
                af[mt][1] = As[buf][r + 8][kk + tig];
                af[mt][2] = As[buf][r][kk + tig + 4];
                af[mt][3] = As[buf][r + 8][kk + tig + 4];
            }
            float bgf[4][2], buf_[4][2];
#pragma unroll
            for (int nt = 0; nt < 4; nt++) {
                int c = wN * 32 + nt * 8 + g;
                bgf[nt][0] = Bsg[buf][kk + tig][c];
                bgf[nt][1] = Bsg[buf][kk + tig + 4][c];
                buf_[nt][0] = Bsu[buf][kk + tig][c];
                buf_[nt][1] = Bsu[buf][kk + tig + 4][c];
            }
#pragma unroll
            for (int nt = 0; nt < 4; nt++)
#pragma unroll
                for (int mt = 0; mt < 2; mt++) {
                    mma_tf32(accg[mt][nt], af[mt], bgf[nt]);
                    mma_tf32(accu[mt][nt], af[mt], buf_[nt]);
                }
        }
    };

    const int nIter = Kd >> 4;
    // prologue: stage tile 0
    LDGf(0);
    STSf(0);
    __syncthreads();
    int cur = 0;
    for (int it = 1; it < nIter; it++) {
        LDGf(it << 4);       // prefetch next tile (hidden under MMAs)
        MMAf(cur);
        STSf(cur ^ 1);
        __syncthreads();
        cur ^= 1;
    }
    MMAf(cur);               // last tile, no staging, no sync

    // epilogue: silu(gate) * up, float2 stores (adjacent columns)
#pragma unroll
    for (int mt = 0; mt < 2; mt++) {
        int r0 = m0 + wM * 32 + mt * 16 + g;
#pragma unroll
        for (int nt = 0; nt < 4; nt++) {
            int c = n0 + wN * 32 + nt * 8 + 2 * tig;
            if (!GATHER || r0 < ne) {
                float2 o;
                o.x = siluf(accg[mt][nt].x) * accu[mt][nt].x;
                o.y = siluf(accg[mt][nt].y) * accu[mt][nt].y;
                *(float2*)(C + (size_t)r0 * N + c) = o;
            }
            if (!GATHER || r0 + 8 < ne) {
                float2 o;
                o.x = siluf(accg[mt][nt].z) * accu[mt][nt].z;
                o.y = siluf(accg[mt][nt].w) * accu[mt][nt].w;
                *(float2*)(C + (size_t)(r0 + 8) * N + c) = o;
            }
        }
    }
}

// ---------------------------------------------------------------------------
// Tensor-core down GEMM, same pipelined tile. N = Hd = 1024.
// SCATTER=false: out = g_hs @ sw_down (plain store, initializes out)
// SCATTER=true : y = g_h[e] @ w_down[e], out[tok] += w * y (atomics)
// ---------------------------------------------------------------------------
template <bool SCATTER>
__global__ void __launch_bounds__(256, 2) down_tc(
    const float* __restrict__ BAll,
    float* __restrict__ out,
    int Kd)
{
    __shared__ __align__(16) float As[2][128][20];
    __shared__ __align__(16) float Bs[2][16][72];
    __shared__ const float* Arow[128];

    const int tid  = threadIdx.x;
    const int lane = tid & 31, wid = tid >> 5;
    const int wM = wid & 3, wN = wid >> 2;
    const int g  = lane >> 2, tig = lane & 3;

    const int n0 = blockIdx.x * 64;
    const int m0 = blockIdx.y * 128;
    const int N = Hd;

    int e = 0, ne = 0;
    const float* B;
    const float* Abase;
    if (SCATTER) {
        e = blockIdx.z;
        ne = g_cnt[e];
        if (m0 >= ne) return;
        B = BAll + (size_t)e * Kd * N;
        Abase = g_h + (size_t)e * CAPn * Id;
    } else {
        B = BAll;
        Abase = g_hs;
    }

    if (tid < 128) {
        int m = m0 + tid;
        const float* p = nullptr;
        if (SCATTER) { if (m < ne) p = Abase + (size_t)m * Kd; }
        else p = Abase + (size_t)m * Kd;
        Arow[tid] = p;
    }
    __syncthreads();

    float4 acc[2][4];
#pragma unroll
    for (int mt = 0; mt < 2; mt++)
#pragma unroll
        for (int nt = 0; nt < 4; nt++) acc[mt][nt] = make_float4(0.f, 0.f, 0.f, 0.f);

    const int mA = tid >> 2;
    const int kq = tid & 3;
    const int kB = tid >> 4;
    const int nq = tid & 15;
    const float* pA0 = Arow[mA];
    const float* pA1 = Arow[mA + 64];
    const float4 z4 = make_float4(0.f, 0.f, 0.f, 0.f);

    float4 rA0, rA1, rB;

    auto LDGf = [&](int k0) {
        rA0 = pA0 ? *(const float4*)(pA0 + k0 + kq * 4) : z4;
        rA1 = pA1 ? *(const float4*)(pA1 + k0 + kq * 4) : z4;
        rB  = *(const float4*)(B + (size_t)(k0 + kB) * N + n0 + nq * 4);
    };
    auto STSf = [&](int buf) {
        *(float4*)&As[buf][mA][kq * 4]      = cvt4(rA0);
        *(float4*)&As[buf][mA + 64][kq * 4] = cvt4(rA1);
        *(float4*)&Bs[buf][kB][nq * 4]      = cvt4(rB);
    };
    auto MMAf = [&](int buf) {
#pragma unroll
        for (int ks = 0; ks < 2; ks++) {
            const int kk = ks * 8;
            float af[2][4];
#pragma unroll
            for (int mt = 0; mt < 2; mt++) {
                int r = wM * 32 + mt * 16 + g;
                af[mt][0] = As[buf][r][kk + tig];
                af[mt][1] = As[buf][r + 8][kk + tig];
                af[mt][2] = As[buf][r][kk + tig + 4];
                af[mt][3] = As[buf][r + 8][kk + tig + 4];
            }
            float bf[4][2];
#pragma unroll
            for (int nt = 0; nt < 4; nt++) {
                int c = wN * 32 + nt * 8 + g;
                bf[nt][0] = Bs[buf][kk + tig][c];
                bf[nt][1] = Bs[buf][kk + tig + 4][c];
            }
#pragma unroll
            for (int nt = 0; nt < 4; nt++)
#pragma unroll
                for (int mt = 0; mt < 2; mt++)
                    mma_tf32(acc[mt][nt], af[mt], bf[nt]);
        }
    };

    const int nIter = Kd >> 4;
    LDGf(0);
    STSf(0);
    __syncthreads();
    int cur = 0;
    for (int it = 1; it < nIter; it++) {
        LDGf(it << 4);
        MMAf(cur);
        STSf(cur ^ 1);
        __syncthreads();
        cur ^= 1;
    }
    MMAf(cur);

#pragma unroll
    for (int mt = 0; mt < 2; mt++) {
        int r0 = m0 + wM * 32 + mt * 16 + g;
#pragma unroll
        for (int nt = 0; nt < 4; nt++) {
            int c = n0 + wN * 32 + nt * 8 + 2 * tig;
            if (SCATTER) {
                if (r0 < ne) {
                    int flat = g_rows[e * CAPn + r0];
                    float wgt = g_topk_w[flat];
                    float* op = out + (size_t)(flat / Kn) * Hd + c;
                    atomicAdd(op + 0, wgt * acc[mt][nt].x);
                    atomicAdd(op + 1, wgt * acc[mt][nt].y);
                }
                if (r0 + 8 < ne) {
                    int flat = g_rows[e * CAPn + r0 + 8];
                    float wgt = g_topk_w[flat];
                    float* op = out + (size_t)(flat / Kn) * Hd + c;
                    atomicAdd(op + 0, wgt * acc[mt][nt].z);
                    atomicAdd(op + 1, wgt * acc[mt][nt].w);
                }
            } else {
                float2 o;
                o.x = acc[mt][nt].x; o.y = acc[mt][nt].y;
                *(float2*)(out + (size_t)r0 * Hd + c) = o;
                o.x = acc[mt][nt].z; o.y = acc[mt][nt].w;
                *(float2*)(out + (size_t)(r0 + 8) * Hd + c) = o;
            }
        }
    }
}

// ---------------------------------------------------------------------------
// Entry point. Inputs (metadata order, all fp32):
// 0:x 1:gate_w 2:w_gate 3:w_up 4:w_down 5:sw_gate 6:sw_up 7:sw_down
// ---------------------------------------------------------------------------
extern "C" void kernel_launch(void* const* d_in, const int* in_sizes, int n_in,
                              void* d_out, int out_size) {
    const float* x       = (const float*)d_in[0];
    const float* gate_w  = (const float*)d_in[1];
    const float* w_gate  = (const float*)d_in[2];
    const float* w_up    = (const float*)d_in[3];
    const float* w_down  = (const float*)d_in[4];
    const float* sw_gate = (const float*)d_in[5];
    const float* sw_up   = (const float*)d_in[6];
    const float* sw_down = (const float*)d_in[7];
    float* out = (float*)d_out;

    gate_kernel<<<Tn, 32>>>(x, gate_w);
    route_kernel<<<En, 256>>>();

    // shared-expert gate/up: (2048 x 1408), K=1024
    gateup_tc<false><<<dim3(Isd / 64, Tn / 128, 1), 256>>>(x, sw_gate, sw_up, Isd, Hd);
    // routed gate/up per expert: (<=768 x 704), K=1024
    gateup_tc<true><<<dim3(Id / 64, CAPn / 128, En), 256>>>(x, w_gate, w_up, Id, Hd);

    // shared-expert down: out = g_hs @ sw_down (initializes every element of out)
    down_tc<false><<<dim3(Hd / 64, Tn / 128, 1), 256>>>(sw_down, out, Isd);
    // routed down + weighted scatter-add (stream-ordered after init)
    down_tc<true><<<dim3(Hd / 64, CAPn / 128, En), 256>>>(w_down, out, Id);
}

// round 16
// speedup vs baseline: 1.4057x; 1.0024x over previous
#include <cuda_runtime.h>
#include <math.h>

// Problem constants (match reference)
#define Tn   2048
#define Hd   1024
#define Id   704
#define Isd  1408
#define En   32
#define TOPG 3
#define Kn   6
#define CAPn 768

// Scratch (no cudaMalloc allowed)
__device__ int   g_topk_idx[Tn * Kn];
__device__ float g_topk_w[Tn * Kn];
__device__ int   g_rows[En * CAPn];   // flat assignment index per (expert, slot)
__device__ int   g_cnt[En];           // clamped count per expert
__device__ float g_h[(size_t)En * CAPn * Id];   // silu(g)*u per expert row
__device__ float g_hs[(size_t)Tn * Isd];        // shared-expert intermediate

__device__ __forceinline__ float siluf(float v) { return v / (1.0f + expf(-v)); }

// fp32 -> tf32 (round to nearest) kept in a float register (bit pattern)
__device__ __forceinline__ float to_tf32(float x) {
    unsigned r;
    asm("cvt.rna.tf32.f32 %0, %1;" : "=r"(r) : "f"(x));
    return __uint_as_float(r);
}
__device__ __forceinline__ float4 cvt4(float4 v) {
    float4 w;
    w.x = to_tf32(v.x); w.y = to_tf32(v.y); w.z = to_tf32(v.z); w.w = to_tf32(v.w);
    return w;
}

// one m16n8k8 tf32 mma, D += A*B
__device__ __forceinline__ void mma_tf32(float4& d, const float* a, const float* b) {
    asm volatile(
        "mma.sync.aligned.m16n8k8.row.col.f32.tf32.tf32.f32 "
        "{%0,%1,%2,%3}, {%4,%5,%6,%7}, {%8,%9}, {%0,%1,%2,%3};"
        : "+f"(d.x), "+f"(d.y), "+f"(d.z), "+f"(d.w)
        : "r"(__float_as_uint(a[0])), "r"(__float_as_uint(a[1])),
          "r"(__float_as_uint(a[2])), "r"(__float_as_uint(a[3])),
          "r"(__float_as_uint(b[0])), "r"(__float_as_uint(b[1])));
}

// ---------------------------------------------------------------------------
// Kernel 1: gating — logits, softmax, group top-3, expert top-6 (jax tie rules)
// one warp per token; lane == expert. Exact fp32 (topk is tie-sensitive).
// ---------------------------------------------------------------------------
__global__ void gate_kernel(const float* __restrict__ x, const float* __restrict__ gw) {
    int t = blockIdx.x;
    int lane = threadIdx.x;
    const float* xr = x + (size_t)t * Hd;
    const float* wr = gw + (size_t)lane * Hd;
    float acc = 0.f;
#pragma unroll 4
    for (int i = 0; i < Hd; i += 4) {
        float4 a = *(const float4*)(xr + i);
        float4 b = *(const float4*)(wr + i);
        acc += a.x * b.x + a.y * b.y + a.z * b.z + a.w * b.w;
    }
    float m = acc;
#pragma unroll
    for (int o = 16; o; o >>= 1) m = fmaxf(m, __shfl_xor_sync(0xffffffffu, m, o));
    float ex = expf(acc - m);
    float s = ex;
#pragma unroll
    for (int o = 16; o; o >>= 1) s += __shfl_xor_sync(0xffffffffu, s, o);
    float score = ex / s;

    float gs = score;
    gs = fmaxf(gs, __shfl_xor_sync(0xffffffffu, gs, 1));
    gs = fmaxf(gs, __shfl_xor_sync(0xffffffffu, gs, 2));
    float grp[8];
#pragma unroll
    for (int g = 0; g < 8; g++) grp[g] = __shfl_sync(0xffffffffu, gs, g * 4);

    bool keep[8];
#pragma unroll
    for (int g = 0; g < 8; g++) keep[g] = false;
    for (int r = 0; r < TOPG; r++) {
        float bv = -1.f; int bi = 0;
#pragma unroll
        for (int g = 0; g < 8; g++)
            if (!keep[g] && grp[g] > bv) { bv = grp[g]; bi = g; }
        keep[bi] = true;
    }
    float v = keep[lane >> 2] ? score : 0.0f;

    for (int r = 0; r < Kn; r++) {
        float bv = v; int bl = lane;
#pragma unroll
        for (int o = 16; o; o >>= 1) {
            float ov = __shfl_xor_sync(0xffffffffu, bv, o);
            int   ol = __shfl_xor_sync(0xffffffffu, bl, o);
            if (ov > bv || (ov == bv && ol < bl)) { bv = ov; bl = ol; }
        }
        if (lane == 0) { g_topk_idx[t * Kn + r] = bl; g_topk_w[t * Kn + r] = bv; }
        if (lane == bl) v = -1.0f;
    }
}

// ---------------------------------------------------------------------------
// Kernel 2: routing — stable rank within expert, capacity drop.
// ---------------------------------------------------------------------------
__global__ void route_kernel() {
    int e = blockIdx.x;
    __shared__ int wsum[8];
    int tid = threadIdx.x, lane = tid & 31, w = tid >> 5;
    int base = 0;
    for (int s = 0; s < Tn * Kn; s += 256) {
        int i = s + tid;
        int matched = (g_topk_idx[i] == e) ? 1 : 0;
        unsigned b = __ballot_sync(0xffffffffu, matched);
        if (lane == 0) wsum[w] = __popc(b);
        __syncthreads();
        int off = base;
        for (int j = 0; j < w; j++) off += wsum[j];
        int pos = off + __popc(b & ((1u << lane) - 1));
        if (matched && pos < CAPn) g_rows[e * CAPn + pos] = i;
        int tot = 0;
#pragma unroll
        for (int j = 0; j < 8; j++) tot += wsum[j];
        base += tot;
        __syncthreads();
    }
    if (tid == 0) g_cnt[e] = (base < CAPn) ? base : CAPn;
}

// ---------------------------------------------------------------------------
// Tensor-core gate/up GEMM: C = silu(A@Bg) * (A@Bu), tf32 mma m16n8k8.
// BM=128, BN=64, BK=16, 256 threads = 8 warps (4M x 2N), warp tile 32x32.
// Double-buffered smem, register prefetch, one __syncthreads per k-step.
// ---------------------------------------------------------------------------
template <bool GATHER>
__global__ void __launch_bounds__(256, 2) gateup_tc(
    const float* __restrict__ X,
    const float* __restrict__ BgAll,
    const float* __restrict__ BuAll,
    int N, int Kd)
{
    __shared__ __align__(16) float As[2][128][20];
    __shared__ __align__(16) float Bsg[2][16][72];
    __shared__ __align__(16) float Bsu[2][16][72];
    __shared__ const float* Arow[128];

    const int tid  = threadIdx.x;
    const int lane = tid & 31, wid = tid >> 5;
    const int wM = wid & 3, wN = wid >> 2;
    const int g  = lane >> 2, tig = lane & 3;

    const int n0 = blockIdx.x * 64;
    const int m0 = blockIdx.y * 128;

    int e = 0, ne = 0;
    const float *Bg, *Bu;
    float* C;
    if (GATHER) {
        e = blockIdx.z;
        ne = g_cnt[e];
        if (m0 >= ne) return;
        Bg = BgAll + (size_t)e * Kd * N;
        Bu = BuAll + (size_t)e * Kd * N;
        C  = g_h + (size_t)e * CAPn * Id;
    } else {
        Bg = BgAll; Bu = BuAll; C = g_hs;
    }

    if (tid < 128) {
        int m = m0 + tid;
        const float* p = nullptr;
        if (GATHER) {
            if (m < ne) p = X + (size_t)(g_rows[e * CAPn + m] / Kn) * Hd;
        } else {
            p = X + (size_t)m * Kd;
        }
        Arow[tid] = p;
    }
    __syncthreads();

    float4 accg[2][4], accu[2][4];
#pragma unroll
    for (int mt = 0; mt < 2; mt++)
#pragma unroll
        for (int nt = 0; nt < 4; nt++) {
            accg[mt][nt] = make_float4(0.f, 0.f, 0.f, 0.f);
            accu[mt][nt] = make_float4(0.f, 0.f, 0.f, 0.f);
        }

    const int mA = tid >> 2;        // 0..63
    const int kq = tid & 3;         // 0..3
    const int kB = tid >> 4;        // 0..15
    const int nq = tid & 15;        // 0..15
    const float* pA0 = Arow[mA];
    const float* pA1 = Arow[mA + 64];
    const float4 z4 = make_float4(0.f, 0.f, 0.f, 0.f);

    float4 rA0, rA1, rBg, rBu;

    auto LDGf = [&](int k0) {
        rA0 = pA0 ? *(const float4*)(pA0 + k0 + kq * 4) : z4;
        rA1 = pA1 ? *(const float4*)(pA1 + k0 + kq * 4) : z4;
        const size_t bo = (size_t)(k0 + kB) * N + n0 + nq * 4;
        rBg = *(const float4*)(Bg + bo);
        rBu = *(const float4*)(Bu + bo);
    };
    auto STSf = [&](int buf) {
        *(float4*)&As[buf][mA][kq * 4]       = cvt4(rA0);
        *(float4*)&As[buf][mA + 64][kq * 4]  = cvt4(rA1);
        *(float4*)&Bsg[buf][kB][nq * 4]      = cvt4(rBg);
        *(float4*)&Bsu[buf][kB][nq * 4]      = cvt4(rBu);
    };
    auto MMAf = [&](int buf) {
#pragma unroll
        for (int ks = 0; ks < 2; ks++) {
            const int kk = ks * 8;
            float af[2][4];
#pragma unroll
            for (int mt = 0; mt < 2; mt++) {
                int r = wM * 32 + mt * 16 + g;
                af[mt][0] = As[buf][r][kk + tig];
                af[mt][1] = As[buf][r + 8][kk + tig];
                af[mt][2] = As[buf][r][kk + tig + 4];
                af[mt][3] = As[buf][r + 8][kk + tig + 4];
            }
            float bgf[4][2], buf_[4][2];
#pragma unroll
            for (int nt = 0; nt < 4; nt++) {
                int c = wN * 32 + nt * 8 + g;
                bgf[nt][0] = Bsg[buf][kk + tig][c];
                bgf[nt][1] = Bsg[buf][kk + tig + 4][c];
                buf_[nt][0] = Bsu[buf][kk + tig][c];
                buf_[nt][1] = Bsu[buf][kk + tig + 4][c];
            }
#pragma unroll
            for (int nt = 0; nt < 4; nt++)
#pragma unroll
                for (int mt = 0; mt < 2; mt++) {
                    mma_tf32(accg[mt][nt], af[mt], bgf[nt]);
                    mma_tf32(accu[mt][nt], af[mt], buf_[nt]);
                }
        }
    };

    const int nIter = Kd >> 4;
    // prologue: stage tile 0
    LDGf(0);
    STSf(0);
    __syncthreads();
    int cur = 0;
    for (int it = 1; it < nIter; it++) {
        LDGf(it << 4);       // prefetch next tile (hidden under MMAs)
        MMAf(cur);
        STSf(cur ^ 1);
        __syncthreads();
        cur ^= 1;
    }
    MMAf(cur);               // last tile, no staging, no sync

    // epilogue: silu(gate) * up, float2 stores (adjacent columns)
#pragma unroll
    for (int mt = 0; mt < 2; mt++) {
        int r0 = m0 + wM * 32 + mt * 16 + g;
#pragma unroll
        for (int nt = 0; nt < 4; nt++) {
            int c = n0 + wN * 32 + nt * 8 + 2 * tig;
            if (!GATHER || r0 < ne) {
                float2 o;
                o.x = siluf(accg[mt][nt].x) * accu[mt][nt].x;
                o.y = siluf(accg[mt][nt].y) * accu[mt][nt].y;
                *(float2*)(C + (size_t)r0 * N + c) = o;
            }
            if (!GATHER || r0 + 8 < ne) {
                float2 o;
                o.x = siluf(accg[mt][nt].z) * accu[mt][nt].z;
                o.y = siluf(accg[mt][nt].w) * accu[mt][nt].w;
                *(float2*)(C + (size_t)(r0 + 8) * N + c) = o;
            }
        }
    }
}

// ---------------------------------------------------------------------------
// Tensor-core down GEMM, same pipelined tile. N = Hd = 1024.
// SCATTER=false: out = g_hs @ sw_down (plain store, initializes out)
// SCATTER=true : y = g_h[e] @ w_down[e], out[tok] += w * y (atomics)
// ---------------------------------------------------------------------------
template <bool SCATTER>
__global__ void __launch_bounds__(256, 2) down_tc(
    const float* __restrict__ BAll,
    float* __restrict__ out,
    int Kd)
{
    __shared__ __align__(16) float As[2][128][20];
    __shared__ __align__(16) float Bs[2][16][72];
    __shared__ const float* Arow[128];

    const int tid  = threadIdx.x;
    const int lane = tid & 31, wid = tid >> 5;
    const int wM = wid & 3, wN = wid >> 2;
    const int g  = lane >> 2, tig = lane & 3;

    const int n0 = blockIdx.x * 64;
    const int m0 = blockIdx.y * 128;
    const int N = Hd;

    int e = 0, ne = 0;
    const float* B;
    const float* Abase;
    if (SCATTER) {
        e = blockIdx.z;
        ne = g_cnt[e];
        if (m0 >= ne) return;
        B = BAll + (size_t)e * Kd * N;
        Abase = g_h + (size_t)e * CAPn * Id;
    } else {
        B = BAll;
        Abase = g_hs;
    }

    if (tid < 128) {
        int m = m0 + tid;
        const float* p = nullptr;
        if (SCATTER) { if (m < ne) p = Abase + (size_t)m * Kd; }
        else p = Abase + (size_t)m * Kd;
        Arow[tid] = p;
    }
    __syncthreads();

    float4 acc[2][4];
#pragma unroll
    for (int mt = 0; mt < 2; mt++)
#pragma unroll
        for (int nt = 0; nt < 4; nt++) acc[mt][nt] = make_float4(0.f, 0.f, 0.f, 0.f);

    const int mA = tid >> 2;
    const int kq = tid & 3;
    const int kB = tid >> 4;
    const int nq = tid & 15;
    const float* pA0 = Arow[mA];
    const float* pA1 = Arow[mA + 64];
    const float4 z4 = make_float4(0.f, 0.f, 0.f, 0.f);

    float4 rA0, rA1, rB;

    auto LDGf = [&](int k0) {
        rA0 = pA0 ? *(const float4*)(pA0 + k0 + kq * 4) : z4;
        rA1 = pA1 ? *(const float4*)(pA1 + k0 + kq * 4) : z4;
        rB  = *(const float4*)(B + (size_t)(k0 + kB) * N + n0 + nq * 4);
    };
    auto STSf = [&](int buf) {
        *(float4*)&As[buf][mA][kq * 4]      = cvt4(rA0);
        *(float4*)&As[buf][mA + 64][kq * 4] = cvt4(rA1);
        *(float4*)&Bs[buf][kB][nq * 4]      = cvt4(rB);
    };
    auto MMAf = [&](int buf) {
#pragma unroll
        for (int ks = 0; ks < 2; ks++) {
            const int kk = ks * 8;
            float af[2][4];
#pragma unroll
            for (int mt = 0; mt < 2; mt++) {
                int r = wM * 32 + mt * 16 + g;
                af[mt][0] = As[buf][r][kk + tig];
                af[mt][1] = As[buf][r + 8][kk + tig];
                af[mt][2] = As[buf][r][kk + tig + 4];
                af[mt][3] = As[buf][r + 8][kk + tig + 4];
            }
            float bf[4][2];
#pragma unroll
            for (int nt = 0; nt < 4; nt++) {
                int c = wN * 32 + nt * 8 + g;
                bf[nt][0] = Bs[buf][kk + tig][c];
                bf[nt][1] = Bs[buf][kk + tig + 4][c];
            }
#pragma unroll
            for (int nt = 0; nt < 4; nt++)
#pragma unroll
                for (int mt = 0; mt < 2; mt++)
                    mma_tf32(acc[mt][nt], af[mt], bf[nt]);
        }
    };

    const int nIter = Kd >> 4;
    LDGf(0);
    STSf(0);
    __syncthreads();
    int cur = 0;
    for (int it = 1; it < nIter; it++) {
        LDGf(it << 4);
        MMAf(cur);
        STSf(cur ^ 1);
        __syncthreads();
        cur ^= 1;
    }
    MMAf(cur);

#pragma unroll
    for (int mt = 0; mt < 2; mt++) {
        int r0 = m0 + wM * 32 + mt * 16 + g;
#pragma unroll
        for (int nt = 0; nt < 4; nt++) {
            int c = n0 + wN * 32 + nt * 8 + 2 * tig;
            if (SCATTER) {
                if (r0 < ne) {
                    int flat = g_rows[e * CAPn + r0];
                    float wgt = g_topk_w[flat];
                    float* op = out + (size_t)(flat / Kn) * Hd + c;
                    atomicAdd(op + 0, wgt * acc[mt][nt].x);
                    atomicAdd(op + 1, wgt * acc[mt][nt].y);
                }
                if (r0 + 8 < ne) {
                    int flat = g_rows[e * CAPn + r0 + 8];
                    float wgt = g_topk_w[flat];
                    float* op = out + (size_t)(flat / Kn) * Hd + c;
                    atomicAdd(op + 0, wgt * acc[mt][nt].z);
                    atomicAdd(op + 1, wgt * acc[mt][nt].w);
                }
            } else {
                float2 o;
                o.x = acc[mt][nt].x; o.y = acc[mt][nt].y;
                *(float2*)(out + (size_t)r0 * Hd + c) = o;
                o.x = acc[mt][nt].z; o.y = acc[mt][nt].w;
                *(float2*)(out + (size_t)(r0 + 8) * Hd + c) = o;
            }
        }
    }
}

// ---------------------------------------------------------------------------
// Entry point. Inputs (metadata order, all fp32):
// 0:x 1:gate_w 2:w_gate 3:w_up 4:w_down 5:sw_gate 6:sw_up 7:sw_down
// ---------------------------------------------------------------------------
extern "C" void kernel_launch(void* const* d_in, const int* in_sizes, int n_in,
                              void* d_out, int out_size) {
    const float* x       = (const float*)d_in[0];
    const float* gate_w  = (const float*)d_in[1];
    const float* w_gate  = (const float*)d_in[2];
    const float* w_up    = (const float*)d_in[3];
    const float* w_down  = (const float*)d_in[4];
    const float* sw_gate = (const float*)d_in[5];
    const float* sw_up   = (const float*)d_in[6];
    const float* sw_down = (const float*)d_in[7];
    float* out = (float*)d_out;

    gate_kernel<<<Tn, 32>>>(x, gate_w);
    route_kernel<<<En, 256>>>();

    // shared-expert gate/up: (2048 x 1408), K=1024
    gateup_tc<false><<<dim3(Isd / 64, Tn / 128, 1), 256>>>(x, sw_gate, sw_up, Isd, Hd);
    // routed gate/up per expert: (<=768 x 704), K=1024
    gateup_tc<true><<<dim3(Id / 64, CAPn / 128, En), 256>>>(x, w_gate, w_up, Id, Hd);

    // shared-expert down: out = g_hs @ sw_down (initializes every element of out)
    down_tc<false><<<dim3(Hd / 64, Tn / 128, 1), 256>>>(sw_down, out, Isd);
    // routed down + weighted scatter-add (stream-ordered after init)
    down_tc<true><<<dim3(Hd / 64, CAPn / 128, En), 256>>>(w_down, out, Id);
}